// round 13
// baseline (speedup 1.0000x reference)
#include <cuda_runtime.h>
#include <cuda_bf16.h>
#include <math.h>
#include <stdint.h>

// Problem constants
#define Bq 2
#define Nq 2048
#define Dq 512
#define Eq 1024
#define Sq 16
#define Kq 4
#define Rq 32
#define Cq 512
#define Mtok (Bq*Nq)   // 4096 tokens
#define NCH 32         // scan chunks
#define NCH_LOG 5
#define CL  64         // chunk length
#define XSPLIT 8       // x_proj split-K factor
#define NBLK_SCAN (Bq*64*NCH)   // 4096

// ---------------- scratch ----------------
__device__ __nv_bfloat16 g_xnb[Mtok*Dq];
__device__ float g_xz[Mtok*2*Eq];
__device__ float g_uc[Mtok*Eq];
__device__ float g_xpart[XSPLIT*Mtok*64];
__device__ float g_xdbl[Mtok*(Rq+2*Sq)];
__device__ float g_delta[Mtok*Eq];
__device__ __nv_bfloat16 g_yb[Mtok*Eq];
__device__ float g_hfin[Bq*NCH*Eq*Sq];
__device__ float g_aprod[Bq*NCH*Eq*Sq];
__device__ float g_gamma[Bq*Dq];
__device__ float g_beta[Bq*Dq];
__device__ __nv_bfloat16 g_wt_in[2*Eq*Dq];
__device__ __nv_bfloat16 g_wt_out[Dq*Eq];
__device__ unsigned g_ticket;
__device__ unsigned g_flags[NBLK_SCAN];

// ---------------- helpers ----------------
__device__ __forceinline__ uint32_t to_tf32(float x) {
    uint32_t r;
    asm("cvt.rna.tf32.f32 %0, %1;" : "=r"(r) : "f"(x));
    return r;
}
__device__ __forceinline__ void cp16(void* smem, const void* gmem) {
    unsigned sa = (unsigned)__cvta_generic_to_shared(smem);
    asm volatile("cp.async.cg.shared.global [%0], [%1], 16;\n" :: "r"(sa), "l"(gmem));
}
__device__ __forceinline__ void cp_commit() {
    asm volatile("cp.async.commit_group;\n");
}
template<int N> __device__ __forceinline__ void cp_wait() {
    asm volatile("cp.async.wait_group %0;\n" :: "n"(N));
}
__device__ __forceinline__ void ldsm_x4(uint32_t r[4], uint32_t addr) {
    asm volatile("ldmatrix.sync.aligned.m8n8.x4.shared.b16 {%0,%1,%2,%3}, [%4];"
        : "=r"(r[0]), "=r"(r[1]), "=r"(r[2]), "=r"(r[3]) : "r"(addr));
}
__device__ __forceinline__ void mma_tf32(float c[4], const uint32_t a[4], const uint32_t b[2]) {
    asm volatile(
        "mma.sync.aligned.m16n8k8.row.col.f32.tf32.tf32.f32 "
        "{%0,%1,%2,%3}, {%4,%5,%6,%7}, {%8,%9}, {%0,%1,%2,%3};"
        : "+f"(c[0]), "+f"(c[1]), "+f"(c[2]), "+f"(c[3])
        : "r"(a[0]), "r"(a[1]), "r"(a[2]), "r"(a[3]),
          "r"(b[0]), "r"(b[1]));
}
__device__ __forceinline__ void mma_bf16(float c[4], const uint32_t a[4], const uint32_t b[2]) {
    asm volatile(
        "mma.sync.aligned.m16n8k16.row.col.f32.bf16.bf16.f32 "
        "{%0,%1,%2,%3}, {%4,%5,%6,%7}, {%8,%9}, {%0,%1,%2,%3};"
        : "+f"(c[0]), "+f"(c[1]), "+f"(c[2]), "+f"(c[3])
        : "r"(a[0]), "r"(a[1]), "r"(a[2]), "r"(a[3]),
          "r"(b[0]), "r"(b[1]));
}

// ---------------- fused prep: W transposes + LayerNorm + FiLM + flag reset ----------------
#define PREP_T1 1024
#define PREP_T2 1536
#define PREP_FILM 1552
#define PREP_LN_END 5648
#define PREP_BLOCKS 5664    // last 16 blocks zero scan flags + ticket
__global__ void __launch_bounds__(256)
prep_kernel(const float* __restrict__ x,
            const float* __restrict__ ln_g, const float* __restrict__ ln_b,
            const float* __restrict__ W_in, const float* __restrict__ W_out,
            const float* __restrict__ cond,
            const float* __restrict__ gw, const float* __restrict__ gb,
            const float* __restrict__ bw, const float* __restrict__ bb,
            __nv_bfloat16* __restrict__ xnb,
            __nv_bfloat16* __restrict__ wt_in, __nv_bfloat16* __restrict__ wt_out,
            float* __restrict__ gamma, float* __restrict__ beta)
{
    __shared__ float sh[33*32];
    int idx = blockIdx.x, tid = threadIdx.x;

    if (idx < PREP_T1) {
        int c0 = (idx & 63) * 32, r0 = (idx >> 6) * 32;
        int tx = tid & 31, ty = tid >> 5;
        #pragma unroll
        for (int i = ty; i < 32; i += 8)
            sh[i*33 + tx] = W_in[(size_t)(r0 + i) * 2048 + c0 + tx];
        __syncthreads();
        #pragma unroll
        for (int i = ty; i < 32; i += 8)
            wt_in[(size_t)(c0 + i) * 512 + r0 + tx] = __float2bfloat16(sh[tx*33 + i]);
    } else if (idx < PREP_T2) {
        int t = idx - PREP_T1;
        int c0 = (t & 15) * 32, r0 = (t >> 4) * 32;
        int tx = tid & 31, ty = tid >> 5;
        #pragma unroll
        for (int i = ty; i < 32; i += 8)
            sh[i*33 + tx] = W_out[(size_t)(r0 + i) * 512 + c0 + tx];
        __syncthreads();
        #pragma unroll
        for (int i = ty; i < 32; i += 8)
            wt_out[(size_t)(c0 + i) * 1024 + r0 + tx] = __float2bfloat16(sh[tx*33 + i]);
    } else if (idx < PREP_FILM) {
        int f = idx - PREP_T2;
        int b = f >> 3, d0 = (f & 7) * 64;
        int dl = tid & 63, cp = tid >> 6;
        float ag = 0.f, ab = 0.f;
        int cbase = cp * 128;
        #pragma unroll 4
        for (int c = cbase; c < cbase + 128; c++) {
            float cv = cond[b * Cq + c];
            ag += cv * gw[c * Dq + d0 + dl];
            ab += cv * bw[c * Dq + d0 + dl];
        }
        sh[cp * 64 + dl] = ag;
        sh[256 + cp * 64 + dl] = ab;
        __syncthreads();
        if (cp == 0) {
            float a = sh[dl] + sh[64 + dl] + sh[128 + dl] + sh[192 + dl];
            float bo = sh[256 + dl] + sh[320 + dl] + sh[384 + dl] + sh[448 + dl];
            gamma[b * Dq + d0 + dl] = a + gb[d0 + dl];
            beta[b * Dq + d0 + dl]  = bo + bb[d0 + dl];
        }
    } else if (idx < PREP_LN_END) {
        int row = idx - PREP_FILM;
        const float* xr = x + (size_t)row * Dq;
        __nv_bfloat16* o = xnb + (size_t)row * Dq;
        int lane = tid & 31, wid = tid >> 5;
        float v0 = xr[tid], v1 = xr[tid + 256];
        float s = v0 + v1;
        #pragma unroll
        for (int o2 = 16; o2; o2 >>= 1) s += __shfl_xor_sync(~0u, s, o2);
        if (lane == 0) sh[wid] = s;
        __syncthreads();
        float mean = (sh[0]+sh[1]+sh[2]+sh[3]+sh[4]+sh[5]+sh[6]+sh[7]) * (1.f / Dq);
        __syncthreads();
        float d0 = v0 - mean, d1 = v1 - mean;
        float vs = d0*d0 + d1*d1;
        #pragma unroll
        for (int o2 = 16; o2; o2 >>= 1) vs += __shfl_xor_sync(~0u, vs, o2);
        if (lane == 0) sh[wid] = vs;
        __syncthreads();
        float rstd = rsqrtf((sh[0]+sh[1]+sh[2]+sh[3]+sh[4]+sh[5]+sh[6]+sh[7]) * (1.f / Dq) + 1e-5f);
        o[tid]       = __float2bfloat16(d0 * rstd * ln_g[tid]       + ln_b[tid]);
        o[tid + 256] = __float2bfloat16(d1 * rstd * ln_g[tid + 256] + ln_b[tid + 256]);
    } else {
        // zero scan flags + ticket
        int z = (idx - PREP_LN_END) * 256 + tid;
        g_flags[z] = 0u;
        if (z == 0) g_ticket = 0u;
    }
}

// ---------------- bf16 tensor-core GEMM (ldmatrix, 3-stage pipeline, BN templated) ----------------
template<int BN, int EPI>
__global__ void __launch_bounds__(256)
gemm_bf16(const __nv_bfloat16* __restrict__ A, const __nv_bfloat16* __restrict__ Bt,
          float* __restrict__ C, int K, int lda, int ldb, int ldc,
          const float* __restrict__ p0, const float* __restrict__ p1)
{
    constexpr int BM = 128, BK = 32;
    constexpr int SL = 40;
    constexpr int FN = BN / 16;
    constexpr int NLB = BN / 64;
    __shared__ __align__(16) __nv_bfloat16 As[3][BM][SL];
    __shared__ __align__(16) __nv_bfloat16 Bs[3][BN][SL];

    int tid = threadIdx.x;
    int warp = tid >> 5, lane = tid & 31;
    int wm = warp & 3, wn = warp >> 2;
    int g = lane >> 2, tq = lane & 3;
    int rowBase = blockIdx.y * BM, colBase = blockIdx.x * BN;

    int aRow = lane & 15, aK = (lane >> 4) * 8;
    int bRow = (lane & 7) | ((lane >> 4) << 3);
    int bK = ((lane >> 3) & 1) * 8;

    uint32_t sA = (uint32_t)__cvta_generic_to_shared(&As[0][0][0]);
    uint32_t sB = (uint32_t)__cvta_generic_to_shared(&Bs[0][0][0]);
    constexpr uint32_t A_BUF = (uint32_t)BM * SL * 2;
    constexpr uint32_t B_BUF = (uint32_t)BN * SL * 2;

    float acc[2][FN][4];
    #pragma unroll
    for (int i = 0; i < 2; i++)
        #pragma unroll
        for (int j = 0; j < FN; j++)
            acc[i][j][0] = acc[i][j][1] = acc[i][j][2] = acc[i][j][3] = 0.f;

    auto prefetch = [&](int k0, int buf) {
        #pragma unroll
        for (int j = 0; j < 2; j++) {
            int f = tid + j * 256;
            int r = f >> 2, c = f & 3;
            cp16(&As[buf][r][c * 8], &A[(size_t)(rowBase + r) * lda + k0 + c * 8]);
        }
        #pragma unroll
        for (int j = 0; j < NLB; j++) {
            int f = tid + j * 256;
            int r = f >> 2, c = f & 3;
            cp16(&Bs[buf][r][c * 8], &Bt[(size_t)(colBase + r) * ldb + k0 + c * 8]);
        }
        cp_commit();
    };

    int KT = K / BK;
    prefetch(0, 0);
    if (KT > 1) prefetch(BK, 1);

    for (int kt = 0; kt < KT; kt++) {
        int buf = kt % 3;
        if (kt + 2 < KT) {
            prefetch((kt + 2) * BK, (kt + 2) % 3);
            cp_wait<2>();
        } else if (kt + 1 < KT) {
            cp_wait<1>();
        } else {
            cp_wait<0>();
        }
        __syncthreads();

        uint32_t sAb = sA + buf * A_BUF;
        uint32_t sBb = sB + buf * B_BUF;

        #pragma unroll
        for (int ks = 0; ks < 2; ks++) {
            int kk = ks * 16;
            uint32_t afr[2][4], bfr[FN][2];
            #pragma unroll
            for (int i = 0; i < 2; i++) {
                uint32_t addr = sAb + ((wm * 32 + i * 16 + aRow) * SL + kk + aK) * 2;
                ldsm_x4(afr[i], addr);
            }
            #pragma unroll
            for (int jj = 0; jj < FN / 2; jj++) {
                uint32_t addr = sBb + ((wn * (BN/2) + jj * 16 + bRow) * SL + kk + bK) * 2;
                uint32_t r[4];
                ldsm_x4(r, addr);
                bfr[2*jj][0] = r[0]; bfr[2*jj][1] = r[1];
                bfr[2*jj+1][0] = r[2]; bfr[2*jj+1][1] = r[3];
            }
            #pragma unroll
            for (int i = 0; i < 2; i++)
                #pragma unroll
                for (int j = 0; j < FN; j++)
                    mma_bf16(acc[i][j], afr[i], bfr[j]);
        }
        __syncthreads();
    }

    #pragma unroll
    for (int i = 0; i < 2; i++) {
        #pragma unroll
        for (int j = 0; j < FN; j++) {
            int row0 = rowBase + wm * 32 + i * 16 + g;
            int col  = colBase + wn * (BN/2) + j * 8 + tq * 2;
            #pragma unroll
            for (int h = 0; h < 2; h++) {
                int row = row0 + h * 8;
                float v0 = acc[i][j][2*h + 0];
                float v1 = acc[i][j][2*h + 1];
                if (EPI == 1) {
                    int bb = row >> 11;
                    v0 = p0[bb * Dq + col + 0] * v0 + p1[bb * Dq + col + 0];
                    v1 = p0[bb * Dq + col + 1] * v1 + p1[bb * Dq + col + 1];
                }
                *(float2*)&C[(size_t)row * ldc + col] = make_float2(v0, v1);
            }
        }
    }
}

// ---------------- TF32 tensor-core GEMM (split-K capable) ----------------
template<int BM, int BN, int BK, int WM, int WN, int EPI>
__global__ void __launch_bounds__(WM*WN*32)
gemm_tf32(const float* __restrict__ A, const float* __restrict__ B,
          float* __restrict__ C, int K, int lda, int ldb, int ldc,
          const float* __restrict__ p0, const float* __restrict__ p1,
          int splitK, size_t splitC)
{
    constexpr int THREADS = WM * WN * 32;
    constexpr int WTM = BM / WM, WTN = BN / WN;
    constexpr int FM = WTM / 16, FN = WTN / 8;
    constexpr int SLA = BK + 4;
    constexpr int SLB = BN + 4;
    constexpr int NLA = BM * BK / 4 / THREADS;
    constexpr int NLB = BK * BN / 4 / THREADS;

    __shared__ __align__(16) float As[2][BM][SLA];
    __shared__ __align__(16) float Bs[2][BK][SLB];

    A += (size_t)blockIdx.z * splitK;
    B += (size_t)blockIdx.z * splitK * ldb;
    C += (size_t)blockIdx.z * splitC;

    int tid = threadIdx.x;
    int warp = tid >> 5, lane = tid & 31;
    int wm = warp % WM, wn = warp / WM;
    int g = lane >> 2, tq = lane & 3;
    int rowBase = blockIdx.y * BM, colBase = blockIdx.x * BN;

    float acc[FM][FN][4];
    #pragma unroll
    for (int i = 0; i < FM; i++)
        #pragma unroll
        for (int j = 0; j < FN; j++)
            acc[i][j][0] = acc[i][j][1] = acc[i][j][2] = acc[i][j][3] = 0.f;

    auto prefetch = [&](int k0, int buf) {
        #pragma unroll
        for (int j = 0; j < NLA; j++) {
            int f = tid + j * THREADS;
            int m = f / (BK/4), k4 = f % (BK/4);
            cp16(&As[buf][m][k4*4], &A[(size_t)(rowBase + m) * lda + k0 + k4*4]);
        }
        #pragma unroll
        for (int j = 0; j < NLB; j++) {
            int f = tid + j * THREADS;
            int k = f / (BN/4), n4 = f % (BN/4);
            cp16(&Bs[buf][k][n4*4], &B[(size_t)(k0 + k) * ldb + colBase + n4*4]);
        }
        cp_commit();
    };

    int KT = K / BK;
    prefetch(0, 0);

    for (int kt = 0; kt < KT; kt++) {
        int buf = kt & 1;
        if (kt + 1 < KT) {
            prefetch((kt + 1) * BK, buf ^ 1);
            cp_wait<1>();
        } else {
            cp_wait<0>();
        }
        __syncthreads();

        #pragma unroll
        for (int ks = 0; ks < BK / 8; ks++) {
            int k0 = ks * 8;
            uint32_t afr[FM][4], bfr[FN][2];
            #pragma unroll
            for (int i = 0; i < FM; i++) {
                int mb = wm * WTM + i * 16;
                afr[i][0] = to_tf32(As[buf][mb + g    ][k0 + tq    ]);
                afr[i][1] = to_tf32(As[buf][mb + g + 8][k0 + tq    ]);
                afr[i][2] = to_tf32(As[buf][mb + g    ][k0 + tq + 4]);
                afr[i][3] = to_tf32(As[buf][mb + g + 8][k0 + tq + 4]);
            }
            #pragma unroll
            for (int j = 0; j < FN; j++) {
                int nb = wn * WTN + j * 8;
                bfr[j][0] = to_tf32(Bs[buf][k0 + tq    ][nb + g]);
                bfr[j][1] = to_tf32(Bs[buf][k0 + tq + 4][nb + g]);
            }
            #pragma unroll
            for (int i = 0; i < FM; i++)
                #pragma unroll
                for (int j = 0; j < FN; j++)
                    mma_tf32(acc[i][j], afr[i], bfr[j]);
        }
        __syncthreads();
    }

    #pragma unroll
    for (int i = 0; i < FM; i++) {
        #pragma unroll
        for (int j = 0; j < FN; j++) {
            int row0 = rowBase + wm * WTM + i * 16 + g;
            int col  = colBase + wn * WTN + j * 8 + tq * 2;
            #pragma unroll
            for (int h = 0; h < 2; h++) {
                int row = row0 + h * 8;
                float v0 = acc[i][j][2*h + 0];
                float v1 = acc[i][j][2*h + 1];
                if (EPI == 2) {
                    v0 += p1[col + 0];
                    v1 += p1[col + 1];
                    v0 = (v0 > 20.f) ? v0 : log1pf(__expf(v0));
                    v1 = (v1 > 20.f) ? v1 : log1pf(__expf(v1));
                }
                *(float2*)&C[(size_t)row * ldc + col] = make_float2(v0, v1);
            }
        }
    }
}

// ---------------- reduce x_proj split-K partials ----------------
__global__ void reduce_xpart(const float* __restrict__ part, float* __restrict__ out)
{
    int i = (blockIdx.x * 256 + threadIdx.x) * 4;
    float4 a = *(const float4*)&part[i];
    #pragma unroll
    for (int s = 1; s < XSPLIT; s++) {
        float4 b = *(const float4*)&part[(size_t)s * Mtok * 64 + i];
        a.x += b.x; a.y += b.y; a.z += b.z; a.w += b.w;
    }
    *(float4*)&out[i] = a;
}

// ---------------- causal depthwise conv + SiLU ----------------
__global__ void conv_silu_kernel(const float* __restrict__ xz,
                                 const float* __restrict__ cw,
                                 const float* __restrict__ cb,
                                 float* __restrict__ uc)
{
    int tid = threadIdx.x;
    int eb = blockIdx.x & 3;
    int tb = blockIdx.x >> 2;
    int e = eb * 256 + tid;
    int tok0 = tb * 8;
    int t0 = tok0 & (Nq - 1);

    float w0 = cw[e*4+0], w1 = cw[e*4+1], w2 = cw[e*4+2], w3 = cw[e*4+3];
    float b = cb[e];
    const float* up = xz + (size_t)tok0 * (2*Eq) + e;

    float xm3 = (t0 > 0) ? up[-3 * 2*Eq] : 0.f;
    float xm2 = (t0 > 0) ? up[-2 * 2*Eq] : 0.f;
    float xm1 = (t0 > 0) ? up[-1 * 2*Eq] : 0.f;
    #pragma unroll
    for (int i = 0; i < 8; i++) {
        float cur = up[(size_t)i * 2*Eq];
        float a = b + xm3*w0 + xm2*w1 + xm1*w2 + cur*w3;
        uc[(size_t)(tok0 + i) * Eq + e] = a / (1.f + __expf(-a));
        xm3 = xm2; xm2 = xm1; xm1 = cur;
    }
}

// ---------------- fused selective scan: summary + decoupled lookback + emit ----------------
__global__ void __launch_bounds__(256)
scan_fused(const float* __restrict__ A_log,
           const float* __restrict__ D_skip,
           const float* __restrict__ xdbl,
           const float* __restrict__ delta,
           const float* __restrict__ uc,
           const float* __restrict__ xz,
           float* __restrict__ hfin,
           float* __restrict__ aprod,
           __nv_bfloat16* __restrict__ y)
{
    __shared__ unsigned s_v;
    int tid = threadIdx.x;
    if (tid == 0) s_v = atomicAdd(&g_ticket, 1u);
    __syncthreads();
    unsigned v = s_v;
    // chunk-major ticket: scheduling order == dependency order -> deadlock-free
    int c  = v >> 7;           // 0..NCH-1
    int b  = (v >> 6) & 1;
    int eb = v & 63;

    int ch = tid >> 4, s = tid & 15;
    int e  = eb * 16 + ch;

    float A  = -__expf(A_log[e * Sq + s]);
    float Dv = D_skip[e];
    size_t tb = (size_t)(b * Nq + c * CL);
    const float* del = delta + tb * Eq + e;
    const float* ucp = uc    + tb * Eq + e;
    const float* dbl = xdbl  + tb * 64;
    const float* zp  = xz    + tb * (2*Eq) + Eq + e;
    __nv_bfloat16* yp = y    + tb * Eq + e;

    // ---- traversal 1: local summary (h0 = 0), pipelined ----
    {
        float dv[4], uv[4], Bv[4];
        #pragma unroll
        for (int j = 0; j < 4; j++) {
            dv[j] = del[(size_t)j * Eq];
            uv[j] = ucp[(size_t)j * Eq];
            Bv[j] = dbl[j * 64 + Rq + s];
        }
        float h = 0.f, asum = 0.f;
        for (int t = 0; t < CL; t += 4) {
            float ndv[4], nuv[4], nBv[4];
            bool more = (t + 4 < CL);
            if (more) {
                #pragma unroll
                for (int j = 0; j < 4; j++) {
                    ndv[j] = del[(size_t)(t + 4 + j) * Eq];
                    nuv[j] = ucp[(size_t)(t + 4 + j) * Eq];
                    nBv[j] = dbl[(t + 4 + j) * 64 + Rq + s];
                }
            }
            float ea[4];
            #pragma unroll
            for (int j = 0; j < 4; j++) ea[j] = __expf(dv[j] * A);
            #pragma unroll
            for (int j = 0; j < 4; j++) {
                h = ea[j] * h + (dv[j] * uv[j]) * Bv[j];
                asum += dv[j];
            }
            if (more) {
                #pragma unroll
                for (int j = 0; j < 4; j++) { dv[j] = ndv[j]; uv[j] = nuv[j]; Bv[j] = nBv[j]; }
            }
        }
        size_t o = (((size_t)(b * NCH + c) * Eq) + e) * Sq + s;
        hfin[o]  = h;
        aprod[o] = __expf(asum * A);
    }
    // publish: data fence from every thread, then flag
    __threadfence();
    __syncthreads();
    if (tid == 0) atomicExch(&g_flags[v], 1u);

    // ---- lookback: combine predecessor summaries in order ----
    float h = 0.f;
    {
        size_t base = (((size_t)(b * NCH) * Eq) + e) * Sq + s;
        unsigned vtail = (v & 127u);
        for (int cc = 0; cc < c; cc++) {
            if (tid == 0) {
                while (atomicAdd(&g_flags[((unsigned)cc << 7) | vtail], 0u) == 0u) { }
            }
            __syncthreads();
            size_t o = base + (size_t)cc * Eq * Sq;
            h = aprod[o] * h + hfin[o];
        }
    }

    // ---- traversal 2: recompute with carry, reduce over S, gate, write y ----
    float dv[4], uv[4], Bv[4], Cv[4], zv[4];
    #pragma unroll
    for (int j = 0; j < 4; j++) {
        dv[j] = del[(size_t)j * Eq];
        uv[j] = ucp[(size_t)j * Eq];
        Bv[j] = dbl[j * 64 + Rq + s];
        Cv[j] = dbl[j * 64 + Rq + Sq + s];
        zv[j] = 0.f;
    }
    if (s == 0) {
        #pragma unroll
        for (int j = 0; j < 4; j++) zv[j] = zp[(size_t)j * (2*Eq)];
    }

    for (int t = 0; t < CL; t += 4) {
        float ndv[4], nuv[4], nBv[4], nCv[4], nzv[4];
        bool more = (t + 4 < CL);
        if (more) {
            #pragma unroll
            for (int j = 0; j < 4; j++) {
                ndv[j] = del[(size_t)(t + 4 + j) * Eq];
                nuv[j] = ucp[(size_t)(t + 4 + j) * Eq];
                nBv[j] = dbl[(t + 4 + j) * 64 + Rq + s];
                nCv[j] = dbl[(t + 4 + j) * 64 + Rq + Sq + s];
            }
            if (s == 0) {
                #pragma unroll
                for (int j = 0; j < 4; j++) nzv[j] = zp[(size_t)(t + 4 + j) * (2*Eq)];
            }
        }

        float ea[4], p[4];
        #pragma unroll
        for (int j = 0; j < 4; j++) ea[j] = __expf(dv[j] * A);
        #pragma unroll
        for (int j = 0; j < 4; j++) {
            h = ea[j] * h + (dv[j] * uv[j]) * Bv[j];
            p[j] = h * Cv[j];
        }
        #pragma unroll
        for (int o2 = 8; o2; o2 >>= 1) {
            #pragma unroll
            for (int j = 0; j < 4; j++)
                p[j] += __shfl_xor_sync(~0u, p[j], o2);
        }
        if (s == 0) {
            #pragma unroll
            for (int j = 0; j < 4; j++) {
                float yv = p[j] + Dv * uv[j];
                float z = zv[j];
                yv *= z / (1.f + __expf(-z));
                yp[(size_t)(t + j) * Eq] = __float2bfloat16(yv);
            }
        }
        if (more) {
            #pragma unroll
            for (int j = 0; j < 4; j++) {
                dv[j] = ndv[j]; uv[j] = nuv[j]; Bv[j] = nBv[j]; Cv[j] = nCv[j];
            }
            if (s == 0) {
                #pragma unroll
                for (int j = 0; j < 4; j++) zv[j] = nzv[j];
            }
        }
    }
}

// ---------------- launch ----------------
extern "C" void kernel_launch(void* const* d_in, const int* in_sizes, int n_in,
                              void* d_out, int out_size)
{
    const float* x       = (const float*)d_in[0];
    const float* cond    = (const float*)d_in[1];
    const float* ln_g    = (const float*)d_in[2];
    const float* ln_b    = (const float*)d_in[3];
    const float* W_in    = (const float*)d_in[4];
    const float* conv_w  = (const float*)d_in[5];
    const float* conv_b  = (const float*)d_in[6];
    const float* W_x     = (const float*)d_in[7];
    const float* W_dt    = (const float*)d_in[8];
    const float* b_dt    = (const float*)d_in[9];
    const float* A_log   = (const float*)d_in[10];
    const float* D_skip  = (const float*)d_in[11];
    const float* W_out   = (const float*)d_in[12];
    const float* film_gw = (const float*)d_in[13];
    const float* film_gb = (const float*)d_in[14];
    const float* film_bw = (const float*)d_in[15];
    const float* film_bb = (const float*)d_in[16];
    float* out = (float*)d_out;

    __nv_bfloat16 *xnb, *yb, *wt_in, *wt_out;
    float *xz, *uc, *xpart, *xdbl, *delta, *hfin, *aprod, *gamma, *beta;
    cudaGetSymbolAddress((void**)&xnb,   g_xnb);
    cudaGetSymbolAddress((void**)&xz,    g_xz);
    cudaGetSymbolAddress((void**)&uc,    g_uc);
    cudaGetSymbolAddress((void**)&xpart, g_xpart);
    cudaGetSymbolAddress((void**)&xdbl,  g_xdbl);
    cudaGetSymbolAddress((void**)&delta, g_delta);
    cudaGetSymbolAddress((void**)&yb,    g_yb);
    cudaGetSymbolAddress((void**)&hfin,  g_hfin);
    cudaGetSymbolAddress((void**)&aprod, g_aprod);
    cudaGetSymbolAddress((void**)&gamma, g_gamma);
    cudaGetSymbolAddress((void**)&beta,  g_beta);
    cudaGetSymbolAddress((void**)&wt_in, g_wt_in);
    cudaGetSymbolAddress((void**)&wt_out,g_wt_out);

    // 1. fused prep: transposes + LN + FiLM + flag/ticket reset
    prep_kernel<<<PREP_BLOCKS, 256>>>(x, ln_g, ln_b, W_in, W_out, cond,
                                      film_gw, film_gb, film_bw, film_bb,
                                      xnb, wt_in, wt_out, gamma, beta);
    // 2. in_proj (BN=64)
    gemm_bf16<64,0><<<dim3(2*Eq/64, Mtok/128), 256>>>(
        xnb, wt_in, xz, Dq, Dq, Dq, 2*Eq, nullptr, nullptr);
    // 3. conv + SiLU
    conv_silu_kernel<<<2048, 256>>>(xz, conv_w, conv_b, uc);
    // 4. x_proj split-K=8
    gemm_tf32<32,64,16,1,4,0><<<dim3(1, Mtok/32, XSPLIT), 128>>>(
        uc, W_x, xpart, Eq/XSPLIT, Eq, Rq + 2*Sq, Rq + 2*Sq, nullptr, nullptr,
        Eq/XSPLIT, (size_t)Mtok * 64);
    reduce_xpart<<<Mtok*64/1024, 256>>>(xpart, xdbl);
    // 5. dt_proj + softplus
    gemm_tf32<128,128,16,4,2,2><<<dim3(Eq/128, Mtok/128), 256>>>(
        xdbl, W_dt, delta, Rq, Rq + 2*Sq, Eq, Eq, nullptr, b_dt, 0, 0);
    // 6. fused scan (summary + lookback + emit)
    scan_fused<<<NBLK_SCAN, 256>>>(A_log, D_skip, xdbl, delta, uc, xz, hfin, aprod, yb);
    // 7. out_proj + FiLM (BN=64)
    gemm_bf16<64,1><<<dim3(Dq/64, Mtok/128), 256>>>(
        yb, wt_out, out, Eq, Eq, Eq, Dq, gamma, beta);
}

// round 14
// speedup vs baseline: 1.2415x; 1.2415x over previous
#include <cuda_runtime.h>
#include <cuda_bf16.h>
#include <math.h>
#include <stdint.h>

// Problem constants
#define Bq 2
#define Nq 2048
#define Dq 512
#define Eq 1024
#define Sq 16
#define Kq 4
#define Rq 32
#define Cq 512
#define Mtok (Bq*Nq)   // 4096 tokens
#define NCH 32         // scan chunks
#define NCH_LOG 5
#define CL  64         // chunk length
#define XSPLIT 8       // x_proj split-K factor

// ---------------- scratch ----------------
__device__ __nv_bfloat16 g_xnb[Mtok*Dq];
__device__ float g_xz[Mtok*2*Eq];
__device__ float g_uc[Mtok*Eq];
__device__ float g_xpart[XSPLIT*Mtok*64];
__device__ float g_xdbl[Mtok*(Rq+2*Sq)];
__device__ float g_delta[Mtok*Eq];
__device__ __nv_bfloat16 g_yb[Mtok*Eq];
__device__ float g_hfin[Bq*NCH*Eq*Sq];
__device__ float g_aprod[Bq*NCH*Eq*Sq];
__device__ float g_gamma[Bq*Dq];
__device__ float g_beta[Bq*Dq];
__device__ __nv_bfloat16 g_wt_in[2*Eq*Dq];
__device__ __nv_bfloat16 g_wt_out[Dq*Eq];

// ---------------- helpers ----------------
__device__ __forceinline__ uint32_t to_tf32(float x) {
    uint32_t r;
    asm("cvt.rna.tf32.f32 %0, %1;" : "=r"(r) : "f"(x));
    return r;
}
__device__ __forceinline__ void cp16(void* smem, const void* gmem) {
    unsigned sa = (unsigned)__cvta_generic_to_shared(smem);
    asm volatile("cp.async.cg.shared.global [%0], [%1], 16;\n" :: "r"(sa), "l"(gmem));
}
__device__ __forceinline__ void cp_commit() {
    asm volatile("cp.async.commit_group;\n");
}
template<int N> __device__ __forceinline__ void cp_wait() {
    asm volatile("cp.async.wait_group %0;\n" :: "n"(N));
}
__device__ __forceinline__ void ldsm_x4(uint32_t r[4], uint32_t addr) {
    asm volatile("ldmatrix.sync.aligned.m8n8.x4.shared.b16 {%0,%1,%2,%3}, [%4];"
        : "=r"(r[0]), "=r"(r[1]), "=r"(r[2]), "=r"(r[3]) : "r"(addr));
}
__device__ __forceinline__ void mma_tf32(float c[4], const uint32_t a[4], const uint32_t b[2]) {
    asm volatile(
        "mma.sync.aligned.m16n8k8.row.col.f32.tf32.tf32.f32 "
        "{%0,%1,%2,%3}, {%4,%5,%6,%7}, {%8,%9}, {%0,%1,%2,%3};"
        : "+f"(c[0]), "+f"(c[1]), "+f"(c[2]), "+f"(c[3])
        : "r"(a[0]), "r"(a[1]), "r"(a[2]), "r"(a[3]),
          "r"(b[0]), "r"(b[1]));
}
__device__ __forceinline__ void mma_bf16(float c[4], const uint32_t a[4], const uint32_t b[2]) {
    asm volatile(
        "mma.sync.aligned.m16n8k16.row.col.f32.bf16.bf16.f32 "
        "{%0,%1,%2,%3}, {%4,%5,%6,%7}, {%8,%9}, {%0,%1,%2,%3};"
        : "+f"(c[0]), "+f"(c[1]), "+f"(c[2]), "+f"(c[3])
        : "r"(a[0]), "r"(a[1]), "r"(a[2]), "r"(a[3]),
          "r"(b[0]), "r"(b[1]));
}

// ---------------- fused prep: W transposes + LayerNorm + FiLM params ----------------
#define PREP_T1 1024
#define PREP_T2 1536
#define PREP_FILM 1552
#define PREP_BLOCKS 5648
__global__ void __launch_bounds__(256)
prep_kernel(const float* __restrict__ x,
            const float* __restrict__ ln_g, const float* __restrict__ ln_b,
            const float* __restrict__ W_in, const float* __restrict__ W_out,
            const float* __restrict__ cond,
            const float* __restrict__ gw, const float* __restrict__ gb,
            const float* __restrict__ bw, const float* __restrict__ bb,
            __nv_bfloat16* __restrict__ xnb,
            __nv_bfloat16* __restrict__ wt_in, __nv_bfloat16* __restrict__ wt_out,
            float* __restrict__ gamma, float* __restrict__ beta)
{
    __shared__ float sh[33*32];
    int idx = blockIdx.x, tid = threadIdx.x;

    if (idx < PREP_T1) {
        int c0 = (idx & 63) * 32, r0 = (idx >> 6) * 32;
        int tx = tid & 31, ty = tid >> 5;
        #pragma unroll
        for (int i = ty; i < 32; i += 8)
            sh[i*33 + tx] = W_in[(size_t)(r0 + i) * 2048 + c0 + tx];
        __syncthreads();
        #pragma unroll
        for (int i = ty; i < 32; i += 8)
            wt_in[(size_t)(c0 + i) * 512 + r0 + tx] = __float2bfloat16(sh[tx*33 + i]);
    } else if (idx < PREP_T2) {
        int t = idx - PREP_T1;
        int c0 = (t & 15) * 32, r0 = (t >> 4) * 32;
        int tx = tid & 31, ty = tid >> 5;
        #pragma unroll
        for (int i = ty; i < 32; i += 8)
            sh[i*33 + tx] = W_out[(size_t)(r0 + i) * 512 + c0 + tx];
        __syncthreads();
        #pragma unroll
        for (int i = ty; i < 32; i += 8)
            wt_out[(size_t)(c0 + i) * 1024 + r0 + tx] = __float2bfloat16(sh[tx*33 + i]);
    } else if (idx < PREP_FILM) {
        int f = idx - PREP_T2;
        int b = f >> 3, d0 = (f & 7) * 64;
        int dl = tid & 63, cp = tid >> 6;
        float ag = 0.f, ab = 0.f;
        int cbase = cp * 128;
        #pragma unroll 4
        for (int c = cbase; c < cbase + 128; c++) {
            float cv = cond[b * Cq + c];
            ag += cv * gw[c * Dq + d0 + dl];
            ab += cv * bw[c * Dq + d0 + dl];
        }
        sh[cp * 64 + dl] = ag;
        sh[256 + cp * 64 + dl] = ab;
        __syncthreads();
        if (cp == 0) {
            float a = sh[dl] + sh[64 + dl] + sh[128 + dl] + sh[192 + dl];
            float bo = sh[256 + dl] + sh[320 + dl] + sh[384 + dl] + sh[448 + dl];
            gamma[b * Dq + d0 + dl] = a + gb[d0 + dl];
            beta[b * Dq + d0 + dl]  = bo + bb[d0 + dl];
        }
    } else {
        int row = idx - PREP_FILM;
        const float* xr = x + (size_t)row * Dq;
        __nv_bfloat16* o = xnb + (size_t)row * Dq;
        int lane = tid & 31, wid = tid >> 5;
        float v0 = xr[tid], v1 = xr[tid + 256];
        float s = v0 + v1;
        #pragma unroll
        for (int o2 = 16; o2; o2 >>= 1) s += __shfl_xor_sync(~0u, s, o2);
        if (lane == 0) sh[wid] = s;
        __syncthreads();
        float mean = (sh[0]+sh[1]+sh[2]+sh[3]+sh[4]+sh[5]+sh[6]+sh[7]) * (1.f / Dq);
        __syncthreads();
        float d0 = v0 - mean, d1 = v1 - mean;
        float vs = d0*d0 + d1*d1;
        #pragma unroll
        for (int o2 = 16; o2; o2 >>= 1) vs += __shfl_xor_sync(~0u, vs, o2);
        if (lane == 0) sh[wid] = vs;
        __syncthreads();
        float rstd = rsqrtf((sh[0]+sh[1]+sh[2]+sh[3]+sh[4]+sh[5]+sh[6]+sh[7]) * (1.f / Dq) + 1e-5f);
        o[tid]       = __float2bfloat16(d0 * rstd * ln_g[tid]       + ln_b[tid]);
        o[tid + 256] = __float2bfloat16(d1 * rstd * ln_g[tid + 256] + ln_b[tid + 256]);
    }
}

// ---------------- bf16 tensor-core GEMM (ldmatrix, 3-stage pipeline, BN templated) ----------------
template<int BN, int EPI>
__global__ void __launch_bounds__(256)
gemm_bf16(const __nv_bfloat16* __restrict__ A, const __nv_bfloat16* __restrict__ Bt,
          float* __restrict__ C, int K, int lda, int ldb, int ldc,
          const float* __restrict__ p0, const float* __restrict__ p1)
{
    constexpr int BM = 128, BK = 32;
    constexpr int SL = 40;
    constexpr int FN = BN / 16;
    constexpr int NLB = BN / 64;
    __shared__ __align__(16) __nv_bfloat16 As[3][BM][SL];
    __shared__ __align__(16) __nv_bfloat16 Bs[3][BN][SL];

    int tid = threadIdx.x;
    int warp = tid >> 5, lane = tid & 31;
    int wm = warp & 3, wn = warp >> 2;
    int g = lane >> 2, tq = lane & 3;
    int rowBase = blockIdx.y * BM, colBase = blockIdx.x * BN;

    int aRow = lane & 15, aK = (lane >> 4) * 8;
    int bRow = (lane & 7) | ((lane >> 4) << 3);
    int bK = ((lane >> 3) & 1) * 8;

    uint32_t sA = (uint32_t)__cvta_generic_to_shared(&As[0][0][0]);
    uint32_t sB = (uint32_t)__cvta_generic_to_shared(&Bs[0][0][0]);
    constexpr uint32_t A_BUF = (uint32_t)BM * SL * 2;
    constexpr uint32_t B_BUF = (uint32_t)BN * SL * 2;

    float acc[2][FN][4];
    #pragma unroll
    for (int i = 0; i < 2; i++)
        #pragma unroll
        for (int j = 0; j < FN; j++)
            acc[i][j][0] = acc[i][j][1] = acc[i][j][2] = acc[i][j][3] = 0.f;

    auto prefetch = [&](int k0, int buf) {
        #pragma unroll
        for (int j = 0; j < 2; j++) {
            int f = tid + j * 256;
            int r = f >> 2, c = f & 3;
            cp16(&As[buf][r][c * 8], &A[(size_t)(rowBase + r) * lda + k0 + c * 8]);
        }
        #pragma unroll
        for (int j = 0; j < NLB; j++) {
            int f = tid + j * 256;
            int r = f >> 2, c = f & 3;
            cp16(&Bs[buf][r][c * 8], &Bt[(size_t)(colBase + r) * ldb + k0 + c * 8]);
        }
        cp_commit();
    };

    int KT = K / BK;
    prefetch(0, 0);
    if (KT > 1) prefetch(BK, 1);

    for (int kt = 0; kt < KT; kt++) {
        int buf = kt % 3;
        if (kt + 2 < KT) {
            prefetch((kt + 2) * BK, (kt + 2) % 3);
            cp_wait<2>();
        } else if (kt + 1 < KT) {
            cp_wait<1>();
        } else {
            cp_wait<0>();
        }
        __syncthreads();

        uint32_t sAb = sA + buf * A_BUF;
        uint32_t sBb = sB + buf * B_BUF;

        #pragma unroll
        for (int ks = 0; ks < 2; ks++) {
            int kk = ks * 16;
            uint32_t afr[2][4], bfr[FN][2];
            #pragma unroll
            for (int i = 0; i < 2; i++) {
                uint32_t addr = sAb + ((wm * 32 + i * 16 + aRow) * SL + kk + aK) * 2;
                ldsm_x4(afr[i], addr);
            }
            #pragma unroll
            for (int jj = 0; jj < FN / 2; jj++) {
                uint32_t addr = sBb + ((wn * (BN/2) + jj * 16 + bRow) * SL + kk + bK) * 2;
                uint32_t r[4];
                ldsm_x4(r, addr);
                bfr[2*jj][0] = r[0]; bfr[2*jj][1] = r[1];
                bfr[2*jj+1][0] = r[2]; bfr[2*jj+1][1] = r[3];
            }
            #pragma unroll
            for (int i = 0; i < 2; i++)
                #pragma unroll
                for (int j = 0; j < FN; j++)
                    mma_bf16(acc[i][j], afr[i], bfr[j]);
        }
        __syncthreads();
    }

    #pragma unroll
    for (int i = 0; i < 2; i++) {
        #pragma unroll
        for (int j = 0; j < FN; j++) {
            int row0 = rowBase + wm * 32 + i * 16 + g;
            int col  = colBase + wn * (BN/2) + j * 8 + tq * 2;
            #pragma unroll
            for (int h = 0; h < 2; h++) {
                int row = row0 + h * 8;
                float v0 = acc[i][j][2*h + 0];
                float v1 = acc[i][j][2*h + 1];
                if (EPI == 1) {
                    int bb = row >> 11;
                    v0 = p0[bb * Dq + col + 0] * v0 + p1[bb * Dq + col + 0];
                    v1 = p0[bb * Dq + col + 1] * v1 + p1[bb * Dq + col + 1];
                }
                *(float2*)&C[(size_t)row * ldc + col] = make_float2(v0, v1);
            }
        }
    }
}

// ---------------- TF32 tensor-core GEMM (split-K capable) ----------------
template<int BM, int BN, int BK, int WM, int WN, int EPI>
__global__ void __launch_bounds__(WM*WN*32)
gemm_tf32(const float* __restrict__ A, const float* __restrict__ B,
          float* __restrict__ C, int K, int lda, int ldb, int ldc,
          const float* __restrict__ p0, const float* __restrict__ p1,
          int splitK, size_t splitC)
{
    constexpr int THREADS = WM * WN * 32;
    constexpr int WTM = BM / WM, WTN = BN / WN;
    constexpr int FM = WTM / 16, FN = WTN / 8;
    constexpr int SLA = BK + 4;
    constexpr int SLB = BN + 4;
    constexpr int NLA = BM * BK / 4 / THREADS;
    constexpr int NLB = BK * BN / 4 / THREADS;

    __shared__ __align__(16) float As[2][BM][SLA];
    __shared__ __align__(16) float Bs[2][BK][SLB];

    A += (size_t)blockIdx.z * splitK;
    B += (size_t)blockIdx.z * splitK * ldb;
    C += (size_t)blockIdx.z * splitC;

    int tid = threadIdx.x;
    int warp = tid >> 5, lane = tid & 31;
    int wm = warp % WM, wn = warp / WM;
    int g = lane >> 2, tq = lane & 3;
    int rowBase = blockIdx.y * BM, colBase = blockIdx.x * BN;

    float acc[FM][FN][4];
    #pragma unroll
    for (int i = 0; i < FM; i++)
        #pragma unroll
        for (int j = 0; j < FN; j++)
            acc[i][j][0] = acc[i][j][1] = acc[i][j][2] = acc[i][j][3] = 0.f;

    auto prefetch = [&](int k0, int buf) {
        #pragma unroll
        for (int j = 0; j < NLA; j++) {
            int f = tid + j * THREADS;
            int m = f / (BK/4), k4 = f % (BK/4);
            cp16(&As[buf][m][k4*4], &A[(size_t)(rowBase + m) * lda + k0 + k4*4]);
        }
        #pragma unroll
        for (int j = 0; j < NLB; j++) {
            int f = tid + j * THREADS;
            int k = f / (BN/4), n4 = f % (BN/4);
            cp16(&Bs[buf][k][n4*4], &B[(size_t)(k0 + k) * ldb + colBase + n4*4]);
        }
        cp_commit();
    };

    int KT = K / BK;
    prefetch(0, 0);

    for (int kt = 0; kt < KT; kt++) {
        int buf = kt & 1;
        if (kt + 1 < KT) {
            prefetch((kt + 1) * BK, buf ^ 1);
            cp_wait<1>();
        } else {
            cp_wait<0>();
        }
        __syncthreads();

        #pragma unroll
        for (int ks = 0; ks < BK / 8; ks++) {
            int k0 = ks * 8;
            uint32_t afr[FM][4], bfr[FN][2];
            #pragma unroll
            for (int i = 0; i < FM; i++) {
                int mb = wm * WTM + i * 16;
                afr[i][0] = to_tf32(As[buf][mb + g    ][k0 + tq    ]);
                afr[i][1] = to_tf32(As[buf][mb + g + 8][k0 + tq    ]);
                afr[i][2] = to_tf32(As[buf][mb + g    ][k0 + tq + 4]);
                afr[i][3] = to_tf32(As[buf][mb + g + 8][k0 + tq + 4]);
            }
            #pragma unroll
            for (int j = 0; j < FN; j++) {
                int nb = wn * WTN + j * 8;
                bfr[j][0] = to_tf32(Bs[buf][k0 + tq    ][nb + g]);
                bfr[j][1] = to_tf32(Bs[buf][k0 + tq + 4][nb + g]);
            }
            #pragma unroll
            for (int i = 0; i < FM; i++)
                #pragma unroll
                for (int j = 0; j < FN; j++)
                    mma_tf32(acc[i][j], afr[i], bfr[j]);
        }
        __syncthreads();
    }

    #pragma unroll
    for (int i = 0; i < FM; i++) {
        #pragma unroll
        for (int j = 0; j < FN; j++) {
            int row0 = rowBase + wm * WTM + i * 16 + g;
            int col  = colBase + wn * WTN + j * 8 + tq * 2;
            #pragma unroll
            for (int h = 0; h < 2; h++) {
                int row = row0 + h * 8;
                float v0 = acc[i][j][2*h + 0];
                float v1 = acc[i][j][2*h + 1];
                if (EPI == 2) {
                    v0 += p1[col + 0];
                    v1 += p1[col + 1];
                    v0 = (v0 > 20.f) ? v0 : log1pf(__expf(v0));
                    v1 = (v1 > 20.f) ? v1 : log1pf(__expf(v1));
                }
                *(float2*)&C[(size_t)row * ldc + col] = make_float2(v0, v1);
            }
        }
    }
}

// ---------------- reduce x_proj split-K partials ----------------
__global__ void reduce_xpart(const float* __restrict__ part, float* __restrict__ out)
{
    int i = (blockIdx.x * 256 + threadIdx.x) * 4;
    float4 a = *(const float4*)&part[i];
    #pragma unroll
    for (int s = 1; s < XSPLIT; s++) {
        float4 b = *(const float4*)&part[(size_t)s * Mtok * 64 + i];
        a.x += b.x; a.y += b.y; a.z += b.z; a.w += b.w;
    }
    *(float4*)&out[i] = a;
}

// ---------------- causal depthwise conv + SiLU ----------------
__global__ void conv_silu_kernel(const float* __restrict__ xz,
                                 const float* __restrict__ cw,
                                 const float* __restrict__ cb,
                                 float* __restrict__ uc)
{
    int tid = threadIdx.x;
    int eb = blockIdx.x & 3;
    int tb = blockIdx.x >> 2;
    int e = eb * 256 + tid;
    int tok0 = tb * 8;
    int t0 = tok0 & (Nq - 1);

    float w0 = cw[e*4+0], w1 = cw[e*4+1], w2 = cw[e*4+2], w3 = cw[e*4+3];
    float b = cb[e];
    const float* up = xz + (size_t)tok0 * (2*Eq) + e;

    float xm3 = (t0 > 0) ? up[-3 * 2*Eq] : 0.f;
    float xm2 = (t0 > 0) ? up[-2 * 2*Eq] : 0.f;
    float xm1 = (t0 > 0) ? up[-1 * 2*Eq] : 0.f;
    #pragma unroll
    for (int i = 0; i < 8; i++) {
        float cur = up[(size_t)i * 2*Eq];
        float a = b + xm3*w0 + xm2*w1 + xm1*w2 + cur*w3;
        uc[(size_t)(tok0 + i) * Eq + e] = a / (1.f + __expf(-a));
        xm3 = xm2; xm2 = xm1; xm1 = cur;
    }
}

// ---------------- chunked selective scan (two-kernel, software-pipelined) ----------------
__global__ void scan_pass1(const float* __restrict__ A_log,
                           const float* __restrict__ xdbl,
                           const float* __restrict__ delta,
                           const float* __restrict__ uc,
                           float* __restrict__ hfin,
                           float* __restrict__ aprod)
{
    int tid = threadIdx.x;
    int ch = tid >> 4, s = tid & 15;
    int c  = blockIdx.x & (NCH - 1);
    int eb = (blockIdx.x >> NCH_LOG) & 63;
    int b  = blockIdx.x >> (NCH_LOG + 6);
    int e  = eb * 16 + ch;

    float A = -__expf(A_log[e * Sq + s]);
    size_t tb = (size_t)(b * Nq + c * CL);
    const float* del = delta + tb * Eq + e;
    const float* ucp = uc    + tb * Eq + e;
    const float* dbl = xdbl  + tb * 64;

    float dv[4], uv[4], Bv[4];
    #pragma unroll
    for (int j = 0; j < 4; j++) {
        dv[j] = del[(size_t)j * Eq];
        uv[j] = ucp[(size_t)j * Eq];
        Bv[j] = dbl[j * 64 + Rq + s];
    }

    float h = 0.f, asum = 0.f;
    for (int t = 0; t < CL; t += 4) {
        float ndv[4], nuv[4], nBv[4];
        bool more = (t + 4 < CL);
        if (more) {
            #pragma unroll
            for (int j = 0; j < 4; j++) {
                ndv[j] = del[(size_t)(t + 4 + j) * Eq];
                nuv[j] = ucp[(size_t)(t + 4 + j) * Eq];
                nBv[j] = dbl[(t + 4 + j) * 64 + Rq + s];
            }
        }
        float ea[4];
        #pragma unroll
        for (int j = 0; j < 4; j++) ea[j] = __expf(dv[j] * A);
        #pragma unroll
        for (int j = 0; j < 4; j++) {
            h = ea[j] * h + (dv[j] * uv[j]) * Bv[j];
            asum += dv[j];
        }
        if (more) {
            #pragma unroll
            for (int j = 0; j < 4; j++) { dv[j] = ndv[j]; uv[j] = nuv[j]; Bv[j] = nBv[j]; }
        }
    }
    size_t o = (((size_t)(b * NCH + c) * Eq) + e) * Sq + s;
    hfin[o]  = h;
    aprod[o] = __expf(asum * A);
}

// pass 3: lookback carry over pass1 chunk summaries (prior launch), recompute + gate + write y
__global__ void scan_pass3(const float* __restrict__ A_log,
                           const float* __restrict__ D_skip,
                           const float* __restrict__ xdbl,
                           const float* __restrict__ delta,
                           const float* __restrict__ uc,
                           const float* __restrict__ xz,
                           const float* __restrict__ hfin,
                           const float* __restrict__ aprod,
                           __nv_bfloat16* __restrict__ y)
{
    int tid = threadIdx.x;
    int ch = tid >> 4, s = tid & 15;
    int c  = blockIdx.x & (NCH - 1);
    int eb = (blockIdx.x >> NCH_LOG) & 63;
    int b  = blockIdx.x >> (NCH_LOG + 6);
    int e  = eb * 16 + ch;

    float A  = -__expf(A_log[e * Sq + s]);
    float Dv = D_skip[e];
    size_t tb = (size_t)(b * Nq + c * CL);
    const float* del = delta + tb * Eq + e;
    const float* ucp = uc    + tb * Eq + e;
    const float* dbl = xdbl  + tb * 64;
    const float* zp  = xz    + tb * (2*Eq) + Eq + e;
    __nv_bfloat16* yp = y    + tb * Eq + e;

    // lookback carry
    float h = 0.f;
    {
        size_t base = (((size_t)(b * NCH) * Eq) + e) * Sq + s;
        for (int cc = 0; cc < c; cc++) {
            size_t o = base + (size_t)cc * Eq * Sq;
            h = aprod[o] * h + hfin[o];
        }
    }

    float dv[4], uv[4], Bv[4], Cv[4], zv[4];
    #pragma unroll
    for (int j = 0; j < 4; j++) {
        dv[j] = del[(size_t)j * Eq];
        uv[j] = ucp[(size_t)j * Eq];
        Bv[j] = dbl[j * 64 + Rq + s];
        Cv[j] = dbl[j * 64 + Rq + Sq + s];
        zv[j] = 0.f;
    }
    if (s == 0) {
        #pragma unroll
        for (int j = 0; j < 4; j++) zv[j] = zp[(size_t)j * (2*Eq)];
    }

    for (int t = 0; t < CL; t += 4) {
        float ndv[4], nuv[4], nBv[4], nCv[4], nzv[4];
        bool more = (t + 4 < CL);
        if (more) {
            #pragma unroll
            for (int j = 0; j < 4; j++) {
                ndv[j] = del[(size_t)(t + 4 + j) * Eq];
                nuv[j] = ucp[(size_t)(t + 4 + j) * Eq];
                nBv[j] = dbl[(t + 4 + j) * 64 + Rq + s];
                nCv[j] = dbl[(t + 4 + j) * 64 + Rq + Sq + s];
            }
            if (s == 0) {
                #pragma unroll
                for (int j = 0; j < 4; j++) nzv[j] = zp[(size_t)(t + 4 + j) * (2*Eq)];
            }
        }

        float ea[4], p[4];
        #pragma unroll
        for (int j = 0; j < 4; j++) ea[j] = __expf(dv[j] * A);
        #pragma unroll
        for (int j = 0; j < 4; j++) {
            h = ea[j] * h + (dv[j] * uv[j]) * Bv[j];
            p[j] = h * Cv[j];
        }
        #pragma unroll
        for (int o2 = 8; o2; o2 >>= 1) {
            #pragma unroll
            for (int j = 0; j < 4; j++)
                p[j] += __shfl_xor_sync(~0u, p[j], o2);
        }
        if (s == 0) {
            #pragma unroll
            for (int j = 0; j < 4; j++) {
                float yv = p[j] + Dv * uv[j];
                float z = zv[j];
                yv *= z / (1.f + __expf(-z));
                yp[(size_t)(t + j) * Eq] = __float2bfloat16(yv);
            }
        }
        if (more) {
            #pragma unroll
            for (int j = 0; j < 4; j++) {
                dv[j] = ndv[j]; uv[j] = nuv[j]; Bv[j] = nBv[j]; Cv[j] = nCv[j];
            }
            if (s == 0) {
                #pragma unroll
                for (int j = 0; j < 4; j++) zv[j] = nzv[j];
            }
        }
    }
}

// ---------------- launch ----------------
extern "C" void kernel_launch(void* const* d_in, const int* in_sizes, int n_in,
                              void* d_out, int out_size)
{
    const float* x       = (const float*)d_in[0];
    const float* cond    = (const float*)d_in[1];
    const float* ln_g    = (const float*)d_in[2];
    const float* ln_b    = (const float*)d_in[3];
    const float* W_in    = (const float*)d_in[4];
    const float* conv_w  = (const float*)d_in[5];
    const float* conv_b  = (const float*)d_in[6];
    const float* W_x     = (const float*)d_in[7];
    const float* W_dt    = (const float*)d_in[8];
    const float* b_dt    = (const float*)d_in[9];
    const float* A_log   = (const float*)d_in[10];
    const float* D_skip  = (const float*)d_in[11];
    const float* W_out   = (const float*)d_in[12];
    const float* film_gw = (const float*)d_in[13];
    const float* film_gb = (const float*)d_in[14];
    const float* film_bw = (const float*)d_in[15];
    const float* film_bb = (const float*)d_in[16];
    float* out = (float*)d_out;

    __nv_bfloat16 *xnb, *yb, *wt_in, *wt_out;
    float *xz, *uc, *xpart, *xdbl, *delta, *hfin, *aprod, *gamma, *beta;
    cudaGetSymbolAddress((void**)&xnb,   g_xnb);
    cudaGetSymbolAddress((void**)&xz,    g_xz);
    cudaGetSymbolAddress((void**)&uc,    g_uc);
    cudaGetSymbolAddress((void**)&xpart, g_xpart);
    cudaGetSymbolAddress((void**)&xdbl,  g_xdbl);
    cudaGetSymbolAddress((void**)&delta, g_delta);
    cudaGetSymbolAddress((void**)&yb,    g_yb);
    cudaGetSymbolAddress((void**)&hfin,  g_hfin);
    cudaGetSymbolAddress((void**)&aprod, g_aprod);
    cudaGetSymbolAddress((void**)&gamma, g_gamma);
    cudaGetSymbolAddress((void**)&beta,  g_beta);
    cudaGetSymbolAddress((void**)&wt_in, g_wt_in);
    cudaGetSymbolAddress((void**)&wt_out,g_wt_out);

    // 1. fused prep: transposes + LN + FiLM params
    prep_kernel<<<PREP_BLOCKS, 256>>>(x, ln_g, ln_b, W_in, W_out, cond,
                                      film_gw, film_gb, film_bw, film_bb,
                                      xnb, wt_in, wt_out, gamma, beta);
    // 2. in_proj (BN=64, 3-stage)
    gemm_bf16<64,0><<<dim3(2*Eq/64, Mtok/128), 256>>>(
        xnb, wt_in, xz, Dq, Dq, Dq, 2*Eq, nullptr, nullptr);
    // 3. conv + SiLU
    conv_silu_kernel<<<2048, 256>>>(xz, conv_w, conv_b, uc);
    // 4. x_proj split-K=8
    gemm_tf32<32,64,16,1,4,0><<<dim3(1, Mtok/32, XSPLIT), 128>>>(
        uc, W_x, xpart, Eq/XSPLIT, Eq, Rq + 2*Sq, Rq + 2*Sq, nullptr, nullptr,
        Eq/XSPLIT, (size_t)Mtok * 64);
    reduce_xpart<<<Mtok*64/1024, 256>>>(xpart, xdbl);
    // 5. dt_proj + softplus
    gemm_tf32<128,128,16,4,2,2><<<dim3(Eq/128, Mtok/128), 256>>>(
        xdbl, W_dt, delta, Rq, Rq + 2*Sq, Eq, Eq, nullptr, b_dt, 0, 0);
    // 6. scan pass1 (chunk summaries)
    scan_pass1<<<Bq*64*NCH, 256>>>(A_log, xdbl, delta, uc, hfin, aprod);
    // 7. scan pass3 with lookback carry
    scan_pass3<<<Bq*64*NCH, 256>>>(A_log, D_skip, xdbl, delta, uc, xz, hfin, aprod, yb);
    // 8. out_proj + FiLM (BN=64, 3-stage)
    gemm_bf16<64,1><<<dim3(Dq/64, Mtok/128), 256>>>(
        yb, wt_out, out, Eq, Eq, Eq, Dq, gamma, beta);
}

// round 16
// speedup vs baseline: 1.3011x; 1.0480x over previous
#include <cuda_runtime.h>
#include <cuda_bf16.h>
#include <math.h>
#include <stdint.h>

// Problem constants
#define Bq 2
#define Nq 2048
#define Dq 512
#define Eq 1024
#define Sq 16
#define Kq 4
#define Rq 32
#define Cq 512
#define Mtok (Bq*Nq)   // 4096 tokens
#define NCH 32         // scan chunks
#define NCH_LOG 5
#define CL  64         // chunk length
#define XSPLIT 8       // x_proj split-K factor

// ---------------- scratch ----------------
__device__ __nv_bfloat16 g_xnb[Mtok*Dq];
__device__ float g_xz[Mtok*2*Eq];
__device__ float g_uc[Mtok*Eq];           // token-major (x_proj)
__device__ float g_ucT[Eq*Mtok];          // e-major (scan)
__device__ float g_xpart[XSPLIT*Mtok*64];
__device__ float g_xdbl[Mtok*(Rq+2*Sq)];
__device__ float g_deltaT[Eq*Mtok];       // e-major (scan)
__device__ __nv_bfloat16 g_yb[Mtok*Eq];
__device__ float g_hfin[Bq*NCH*Eq*Sq];
__device__ float g_aprod[Bq*NCH*Eq*Sq];
__device__ float g_gamma[Bq*Dq];
__device__ float g_beta[Bq*Dq];
__device__ __nv_bfloat16 g_wt_in[2*Eq*Dq];
__device__ __nv_bfloat16 g_wt_out[Dq*Eq];

// ---------------- helpers ----------------
__device__ __forceinline__ uint32_t to_tf32(float x) {
    uint32_t r;
    asm("cvt.rna.tf32.f32 %0, %1;" : "=r"(r) : "f"(x));
    return r;
}
__device__ __forceinline__ void cp16(void* smem, const void* gmem) {
    unsigned sa = (unsigned)__cvta_generic_to_shared(smem);
    asm volatile("cp.async.cg.shared.global [%0], [%1], 16;\n" :: "r"(sa), "l"(gmem));
}
__device__ __forceinline__ void cp_commit() {
    asm volatile("cp.async.commit_group;\n");
}
template<int N> __device__ __forceinline__ void cp_wait() {
    asm volatile("cp.async.wait_group %0;\n" :: "n"(N));
}
__device__ __forceinline__ void ldsm_x4(uint32_t r[4], uint32_t addr) {
    asm volatile("ldmatrix.sync.aligned.m8n8.x4.shared.b16 {%0,%1,%2,%3}, [%4];"
        : "=r"(r[0]), "=r"(r[1]), "=r"(r[2]), "=r"(r[3]) : "r"(addr));
}
__device__ __forceinline__ void mma_tf32(float c[4], const uint32_t a[4], const uint32_t b[2]) {
    asm volatile(
        "mma.sync.aligned.m16n8k8.row.col.f32.tf32.tf32.f32 "
        "{%0,%1,%2,%3}, {%4,%5,%6,%7}, {%8,%9}, {%0,%1,%2,%3};"
        : "+f"(c[0]), "+f"(c[1]), "+f"(c[2]), "+f"(c[3])
        : "r"(a[0]), "r"(a[1]), "r"(a[2]), "r"(a[3]),
          "r"(b[0]), "r"(b[1]));
}
__device__ __forceinline__ void mma_bf16(float c[4], const uint32_t a[4], const uint32_t b[2]) {
    asm volatile(
        "mma.sync.aligned.m16n8k16.row.col.f32.bf16.bf16.f32 "
        "{%0,%1,%2,%3}, {%4,%5,%6,%7}, {%8,%9}, {%0,%1,%2,%3};"
        : "+f"(c[0]), "+f"(c[1]), "+f"(c[2]), "+f"(c[3])
        : "r"(a[0]), "r"(a[1]), "r"(a[2]), "r"(a[3]),
          "r"(b[0]), "r"(b[1]));
}

// ---------------- fused prep: W transposes + LayerNorm + FiLM params ----------------
#define PREP_T1 1024
#define PREP_T2 1536
#define PREP_FILM 1552
#define PREP_BLOCKS 5648
__global__ void __launch_bounds__(256)
prep_kernel(const float* __restrict__ x,
            const float* __restrict__ ln_g, const float* __restrict__ ln_b,
            const float* __restrict__ W_in, const float* __restrict__ W_out,
            const float* __restrict__ cond,
            const float* __restrict__ gw, const float* __restrict__ gb,
            const float* __restrict__ bw, const float* __restrict__ bb,
            __nv_bfloat16* __restrict__ xnb,
            __nv_bfloat16* __restrict__ wt_in, __nv_bfloat16* __restrict__ wt_out,
            float* __restrict__ gamma, float* __restrict__ beta)
{
    __shared__ float sh[33*32];
    int idx = blockIdx.x, tid = threadIdx.x;

    if (idx < PREP_T1) {
        int c0 = (idx & 63) * 32, r0 = (idx >> 6) * 32;
        int tx = tid & 31, ty = tid >> 5;
        #pragma unroll
        for (int i = ty; i < 32; i += 8)
            sh[i*33 + tx] = W_in[(size_t)(r0 + i) * 2048 + c0 + tx];
        __syncthreads();
        #pragma unroll
        for (int i = ty; i < 32; i += 8)
            wt_in[(size_t)(c0 + i) * 512 + r0 + tx] = __float2bfloat16(sh[tx*33 + i]);
    } else if (idx < PREP_T2) {
        int t = idx - PREP_T1;
        int c0 = (t & 15) * 32, r0 = (t >> 4) * 32;
        int tx = tid & 31, ty = tid >> 5;
        #pragma unroll
        for (int i = ty; i < 32; i += 8)
            sh[i*33 + tx] = W_out[(size_t)(r0 + i) * 512 + c0 + tx];
        __syncthreads();
        #pragma unroll
        for (int i = ty; i < 32; i += 8)
            wt_out[(size_t)(c0 + i) * 1024 + r0 + tx] = __float2bfloat16(sh[tx*33 + i]);
    } else if (idx < PREP_FILM) {
        int f = idx - PREP_T2;
        int b = f >> 3, d0 = (f & 7) * 64;
        int dl = tid & 63, cp = tid >> 6;
        float ag = 0.f, ab = 0.f;
        int cbase = cp * 128;
        #pragma unroll 4
        for (int c = cbase; c < cbase + 128; c++) {
            float cv = cond[b * Cq + c];
            ag += cv * gw[c * Dq + d0 + dl];
            ab += cv * bw[c * Dq + d0 + dl];
        }
        sh[cp * 64 + dl] = ag;
        sh[256 + cp * 64 + dl] = ab;
        __syncthreads();
        if (cp == 0) {
            float a = sh[dl] + sh[64 + dl] + sh[128 + dl] + sh[192 + dl];
            float bo = sh[256 + dl] + sh[320 + dl] + sh[384 + dl] + sh[448 + dl];
            gamma[b * Dq + d0 + dl] = a + gb[d0 + dl];
            beta[b * Dq + d0 + dl]  = bo + bb[d0 + dl];
        }
    } else {
        int row = idx - PREP_FILM;
        const float* xr = x + (size_t)row * Dq;
        __nv_bfloat16* o = xnb + (size_t)row * Dq;
        int lane = tid & 31, wid = tid >> 5;
        float v0 = xr[tid], v1 = xr[tid + 256];
        float s = v0 + v1;
        #pragma unroll
        for (int o2 = 16; o2; o2 >>= 1) s += __shfl_xor_sync(~0u, s, o2);
        if (lane == 0) sh[wid] = s;
        __syncthreads();
        float mean = (sh[0]+sh[1]+sh[2]+sh[3]+sh[4]+sh[5]+sh[6]+sh[7]) * (1.f / Dq);
        __syncthreads();
        float d0 = v0 - mean, d1 = v1 - mean;
        float vs = d0*d0 + d1*d1;
        #pragma unroll
        for (int o2 = 16; o2; o2 >>= 1) vs += __shfl_xor_sync(~0u, vs, o2);
        if (lane == 0) sh[wid] = vs;
        __syncthreads();
        float rstd = rsqrtf((sh[0]+sh[1]+sh[2]+sh[3]+sh[4]+sh[5]+sh[6]+sh[7]) * (1.f / Dq) + 1e-5f);
        o[tid]       = __float2bfloat16(d0 * rstd * ln_g[tid]       + ln_b[tid]);
        o[tid + 256] = __float2bfloat16(d1 * rstd * ln_g[tid + 256] + ln_b[tid + 256]);
    }
}

// ---------------- bf16 tensor-core GEMM (ldmatrix, 3-stage pipeline, BN templated) ----------------
template<int BN, int EPI>
__global__ void __launch_bounds__(256)
gemm_bf16(const __nv_bfloat16* __restrict__ A, const __nv_bfloat16* __restrict__ Bt,
          float* __restrict__ C, int K, int lda, int ldb, int ldc,
          const float* __restrict__ p0, const float* __restrict__ p1)
{
    constexpr int BM = 128, BK = 32;
    constexpr int SL = 40;
    constexpr int FN = BN / 16;
    constexpr int NLB = BN / 64;
    __shared__ __align__(16) __nv_bfloat16 As[3][BM][SL];
    __shared__ __align__(16) __nv_bfloat16 Bs[3][BN][SL];

    int tid = threadIdx.x;
    int warp = tid >> 5, lane = tid & 31;
    int wm = warp & 3, wn = warp >> 2;
    int g = lane >> 2, tq = lane & 3;
    int rowBase = blockIdx.y * BM, colBase = blockIdx.x * BN;

    int aRow = lane & 15, aK = (lane >> 4) * 8;
    int bRow = (lane & 7) | ((lane >> 4) << 3);
    int bK = ((lane >> 3) & 1) * 8;

    uint32_t sA = (uint32_t)__cvta_generic_to_shared(&As[0][0][0]);
    uint32_t sB = (uint32_t)__cvta_generic_to_shared(&Bs[0][0][0]);
    constexpr uint32_t A_BUF = (uint32_t)BM * SL * 2;
    constexpr uint32_t B_BUF = (uint32_t)BN * SL * 2;

    float acc[2][FN][4];
    #pragma unroll
    for (int i = 0; i < 2; i++)
        #pragma unroll
        for (int j = 0; j < FN; j++)
            acc[i][j][0] = acc[i][j][1] = acc[i][j][2] = acc[i][j][3] = 0.f;

    auto prefetch = [&](int k0, int buf) {
        #pragma unroll
        for (int j = 0; j < 2; j++) {
            int f = tid + j * 256;
            int r = f >> 2, c = f & 3;
            cp16(&As[buf][r][c * 8], &A[(size_t)(rowBase + r) * lda + k0 + c * 8]);
        }
        #pragma unroll
        for (int j = 0; j < NLB; j++) {
            int f = tid + j * 256;
            int r = f >> 2, c = f & 3;
            cp16(&Bs[buf][r][c * 8], &Bt[(size_t)(colBase + r) * ldb + k0 + c * 8]);
        }
        cp_commit();
    };

    int KT = K / BK;
    prefetch(0, 0);
    if (KT > 1) prefetch(BK, 1);

    for (int kt = 0; kt < KT; kt++) {
        int buf = kt % 3;
        if (kt + 2 < KT) {
            prefetch((kt + 2) * BK, (kt + 2) % 3);
            cp_wait<2>();
        } else if (kt + 1 < KT) {
            cp_wait<1>();
        } else {
            cp_wait<0>();
        }
        __syncthreads();

        uint32_t sAb = sA + buf * A_BUF;
        uint32_t sBb = sB + buf * B_BUF;

        #pragma unroll
        for (int ks = 0; ks < 2; ks++) {
            int kk = ks * 16;
            uint32_t afr[2][4], bfr[FN][2];
            #pragma unroll
            for (int i = 0; i < 2; i++) {
                uint32_t addr = sAb + ((wm * 32 + i * 16 + aRow) * SL + kk + aK) * 2;
                ldsm_x4(afr[i], addr);
            }
            #pragma unroll
            for (int jj = 0; jj < FN / 2; jj++) {
                uint32_t addr = sBb + ((wn * (BN/2) + jj * 16 + bRow) * SL + kk + bK) * 2;
                uint32_t r[4];
                ldsm_x4(r, addr);
                bfr[2*jj][0] = r[0]; bfr[2*jj][1] = r[1];
                bfr[2*jj+1][0] = r[2]; bfr[2*jj+1][1] = r[3];
            }
            #pragma unroll
            for (int i = 0; i < 2; i++)
                #pragma unroll
                for (int j = 0; j < FN; j++)
                    mma_bf16(acc[i][j], afr[i], bfr[j]);
        }
        __syncthreads();
    }

    #pragma unroll
    for (int i = 0; i < 2; i++) {
        #pragma unroll
        for (int j = 0; j < FN; j++) {
            int row0 = rowBase + wm * 32 + i * 16 + g;
            int col  = colBase + wn * (BN/2) + j * 8 + tq * 2;
            #pragma unroll
            for (int h = 0; h < 2; h++) {
                int row = row0 + h * 8;
                float v0 = acc[i][j][2*h + 0];
                float v1 = acc[i][j][2*h + 1];
                if (EPI == 1) {
                    int bb = row >> 11;
                    v0 = p0[bb * Dq + col + 0] * v0 + p1[bb * Dq + col + 0];
                    v1 = p0[bb * Dq + col + 1] * v1 + p1[bb * Dq + col + 1];
                }
                *(float2*)&C[(size_t)row * ldc + col] = make_float2(v0, v1);
            }
        }
    }
}

// ---------------- TF32 tensor-core GEMM (split-K; EPI 2 = softplus + TRANSPOSED store) ----------------
template<int BM, int BN, int BK, int WM, int WN, int EPI>
__global__ void __launch_bounds__(WM*WN*32)
gemm_tf32(const float* __restrict__ A, const float* __restrict__ B,
          float* __restrict__ C, int K, int lda, int ldb, int ldc,
          const float* __restrict__ p0, const float* __restrict__ p1,
          int splitK, size_t splitC)
{
    constexpr int THREADS = WM * WN * 32;
    constexpr int WTM = BM / WM, WTN = BN / WN;
    constexpr int FM = WTM / 16, FN = WTN / 8;
    constexpr int SLA = BK + 4;
    constexpr int SLB = BN + 4;
    constexpr int NLA = BM * BK / 4 / THREADS;
    constexpr int NLB = BK * BN / 4 / THREADS;

    __shared__ __align__(16) float As[2][BM][SLA];
    __shared__ __align__(16) float Bs[2][BK][SLB];

    A += (size_t)blockIdx.z * splitK;
    B += (size_t)blockIdx.z * splitK * ldb;
    C += (size_t)blockIdx.z * splitC;

    int tid = threadIdx.x;
    int warp = tid >> 5, lane = tid & 31;
    int wm = warp % WM, wn = warp / WM;
    int g = lane >> 2, tq = lane & 3;
    int rowBase = blockIdx.y * BM, colBase = blockIdx.x * BN;

    float acc[FM][FN][4];
    #pragma unroll
    for (int i = 0; i < FM; i++)
        #pragma unroll
        for (int j = 0; j < FN; j++)
            acc[i][j][0] = acc[i][j][1] = acc[i][j][2] = acc[i][j][3] = 0.f;

    auto prefetch = [&](int k0, int buf) {
        #pragma unroll
        for (int j = 0; j < NLA; j++) {
            int f = tid + j * THREADS;
            int m = f / (BK/4), k4 = f % (BK/4);
            cp16(&As[buf][m][k4*4], &A[(size_t)(rowBase + m) * lda + k0 + k4*4]);
        }
        #pragma unroll
        for (int j = 0; j < NLB; j++) {
            int f = tid + j * THREADS;
            int k = f / (BN/4), n4 = f % (BN/4);
            cp16(&Bs[buf][k][n4*4], &B[(size_t)(k0 + k) * ldb + colBase + n4*4]);
        }
        cp_commit();
    };

    int KT = K / BK;
    prefetch(0, 0);

    for (int kt = 0; kt < KT; kt++) {
        int buf = kt & 1;
        if (kt + 1 < KT) {
            prefetch((kt + 1) * BK, buf ^ 1);
            cp_wait<1>();
        } else {
            cp_wait<0>();
        }
        __syncthreads();

        #pragma unroll
        for (int ks = 0; ks < BK / 8; ks++) {
            int k0 = ks * 8;
            uint32_t afr[FM][4], bfr[FN][2];
            #pragma unroll
            for (int i = 0; i < FM; i++) {
                int mb = wm * WTM + i * 16;
                afr[i][0] = to_tf32(As[buf][mb + g    ][k0 + tq    ]);
                afr[i][1] = to_tf32(As[buf][mb + g + 8][k0 + tq    ]);
                afr[i][2] = to_tf32(As[buf][mb + g    ][k0 + tq + 4]);
                afr[i][3] = to_tf32(As[buf][mb + g + 8][k0 + tq + 4]);
            }
            #pragma unroll
            for (int j = 0; j < FN; j++) {
                int nb = wn * WTN + j * 8;
                bfr[j][0] = to_tf32(Bs[buf][k0 + tq    ][nb + g]);
                bfr[j][1] = to_tf32(Bs[buf][k0 + tq + 4][nb + g]);
            }
            #pragma unroll
            for (int i = 0; i < FM; i++)
                #pragma unroll
                for (int j = 0; j < FN; j++)
                    mma_tf32(acc[i][j], afr[i], bfr[j]);
        }
        __syncthreads();
    }

    #pragma unroll
    for (int i = 0; i < FM; i++) {
        #pragma unroll
        for (int j = 0; j < FN; j++) {
            int row0 = rowBase + wm * WTM + i * 16 + g;
            int col  = colBase + wn * WTN + j * 8 + tq * 2;
            #pragma unroll
            for (int h = 0; h < 2; h++) {
                int row = row0 + h * 8;
                float v0 = acc[i][j][2*h + 0];
                float v1 = acc[i][j][2*h + 1];
                if (EPI == 2) {
                    v0 += p1[col + 0];
                    v1 += p1[col + 1];
                    v0 = (v0 > 20.f) ? v0 : log1pf(__expf(v0));
                    v1 = (v1 > 20.f) ? v1 : log1pf(__expf(v1));
                    // transposed store: C[e][token]
                    C[(size_t)(col + 0) * Mtok + row] = v0;
                    C[(size_t)(col + 1) * Mtok + row] = v1;
                } else {
                    *(float2*)&C[(size_t)row * ldc + col] = make_float2(v0, v1);
                }
            }
        }
    }
}

// ---------------- reduce x_proj split-K partials ----------------
__global__ void reduce_xpart(const float* __restrict__ part, float* __restrict__ out)
{
    int i = (blockIdx.x * 256 + threadIdx.x) * 4;
    float4 a = *(const float4*)&part[i];
    #pragma unroll
    for (int s = 1; s < XSPLIT; s++) {
        float4 b = *(const float4*)&part[(size_t)s * Mtok * 64 + i];
        a.x += b.x; a.y += b.y; a.z += b.z; a.w += b.w;
    }
    *(float4*)&out[i] = a;
}

// ---------------- causal depthwise conv + SiLU (dual-layout output) ----------------
__global__ void conv_silu_kernel(const float* __restrict__ xz,
                                 const float* __restrict__ cw,
                                 const float* __restrict__ cb,
                                 float* __restrict__ uc,
                                 float* __restrict__ ucT)
{
    int tid = threadIdx.x;
    int eb = blockIdx.x & 3;
    int tb = blockIdx.x >> 2;
    int e = eb * 256 + tid;
    int tok0 = tb * 8;
    int t0 = tok0 & (Nq - 1);

    float w0 = cw[e*4+0], w1 = cw[e*4+1], w2 = cw[e*4+2], w3 = cw[e*4+3];
    float b = cb[e];
    const float* up = xz + (size_t)tok0 * (2*Eq) + e;

    float xm3 = (t0 > 0) ? up[-3 * 2*Eq] : 0.f;
    float xm2 = (t0 > 0) ? up[-2 * 2*Eq] : 0.f;
    float xm1 = (t0 > 0) ? up[-1 * 2*Eq] : 0.f;
    float outv[8];
    #pragma unroll
    for (int i = 0; i < 8; i++) {
        float cur = up[(size_t)i * 2*Eq];
        float a = b + xm3*w0 + xm2*w1 + xm1*w2 + cur*w3;
        float v = a / (1.f + __expf(-a));
        uc[(size_t)(tok0 + i) * Eq + e] = v;
        outv[i] = v;
        xm3 = xm2; xm2 = xm1; xm1 = cur;
    }
    float* tp = ucT + (size_t)e * Mtok + tok0;
    *(float4*)&tp[0] = make_float4(outv[0], outv[1], outv[2], outv[3]);
    *(float4*)&tp[4] = make_float4(outv[4], outv[5], outv[6], outv[7]);
}

// ---------------- chunked selective scan (e-major dv/uv, float4 loads) ----------------
__global__ void scan_pass1(const float* __restrict__ A_log,
                           const float* __restrict__ xdbl,
                           const float* __restrict__ deltaT,
                           const float* __restrict__ ucT,
                           float* __restrict__ hfin,
                           float* __restrict__ aprod)
{
    int tid = threadIdx.x;
    int ch = tid >> 4, s = tid & 15;
    int c  = blockIdx.x & (NCH - 1);
    int eb = (blockIdx.x >> NCH_LOG) & 63;
    int b  = blockIdx.x >> (NCH_LOG + 6);
    int e  = eb * 16 + ch;

    float A = -__expf(A_log[e * Sq + s]);
    size_t tok0 = (size_t)(b * Nq + c * CL);
    const float* del = deltaT + (size_t)e * Mtok + tok0;
    const float* ucp = ucT    + (size_t)e * Mtok + tok0;
    const float* dbl = xdbl   + tok0 * 64;

    float4 dv = *(const float4*)&del[0];
    float4 uv = *(const float4*)&ucp[0];
    float Bv[4];
    #pragma unroll
    for (int j = 0; j < 4; j++) Bv[j] = dbl[j * 64 + Rq + s];

    float h = 0.f, asum = 0.f;
    for (int t = 0; t < CL; t += 4) {
        float4 ndv, nuv;
        float nBv[4];
        bool more = (t + 4 < CL);
        if (more) {
            ndv = *(const float4*)&del[t + 4];
            nuv = *(const float4*)&ucp[t + 4];
            #pragma unroll
            for (int j = 0; j < 4; j++) nBv[j] = dbl[(t + 4 + j) * 64 + Rq + s];
        }
        float d[4] = {dv.x, dv.y, dv.z, dv.w};
        float u[4] = {uv.x, uv.y, uv.z, uv.w};
        float ea[4];
        #pragma unroll
        for (int j = 0; j < 4; j++) ea[j] = __expf(d[j] * A);
        #pragma unroll
        for (int j = 0; j < 4; j++) {
            h = ea[j] * h + (d[j] * u[j]) * Bv[j];
            asum += d[j];
        }
        if (more) {
            dv = ndv; uv = nuv;
            #pragma unroll
            for (int j = 0; j < 4; j++) Bv[j] = nBv[j];
        }
    }
    size_t o = (((size_t)(b * NCH + c) * Eq) + e) * Sq + s;
    hfin[o]  = h;
    aprod[o] = __expf(asum * A);
}

__global__ void scan_pass3(const float* __restrict__ A_log,
                           const float* __restrict__ D_skip,
                           const float* __restrict__ xdbl,
                           const float* __restrict__ deltaT,
                           const float* __restrict__ ucT,
                           const float* __restrict__ xz,
                           const float* __restrict__ hfin,
                           const float* __restrict__ aprod,
                           __nv_bfloat16* __restrict__ y)
{
    int tid = threadIdx.x;
    int ch = tid >> 4, s = tid & 15;
    int c  = blockIdx.x & (NCH - 1);
    int eb = (blockIdx.x >> NCH_LOG) & 63;
    int b  = blockIdx.x >> (NCH_LOG + 6);
    int e  = eb * 16 + ch;

    float A  = -__expf(A_log[e * Sq + s]);
    float Dv = D_skip[e];
    size_t tok0 = (size_t)(b * Nq + c * CL);
    const float* del = deltaT + (size_t)e * Mtok + tok0;
    const float* ucp = ucT    + (size_t)e * Mtok + tok0;
    const float* dbl = xdbl   + tok0 * 64;
    const float* zp  = xz     + tok0 * (2*Eq) + Eq + e;
    __nv_bfloat16* yp = y     + tok0 * Eq + e;

    // lookback carry
    float h = 0.f;
    {
        size_t base = (((size_t)(b * NCH) * Eq) + e) * Sq + s;
        for (int cc = 0; cc < c; cc++) {
            size_t o = base + (size_t)cc * Eq * Sq;
            h = aprod[o] * h + hfin[o];
        }
    }

    float4 dv = *(const float4*)&del[0];
    float4 uv = *(const float4*)&ucp[0];
    float Bv[4], Cv[4], zv[4];
    #pragma unroll
    for (int j = 0; j < 4; j++) {
        Bv[j] = dbl[j * 64 + Rq + s];
        Cv[j] = dbl[j * 64 + Rq + Sq + s];
        zv[j] = 0.f;
    }
    if (s == 0) {
        #pragma unroll
        for (int j = 0; j < 4; j++) zv[j] = zp[(size_t)j * (2*Eq)];
    }

    for (int t = 0; t < CL; t += 4) {
        float4 ndv, nuv;
        float nBv[4], nCv[4], nzv[4];
        bool more = (t + 4 < CL);
        if (more) {
            ndv = *(const float4*)&del[t + 4];
            nuv = *(const float4*)&ucp[t + 4];
            #pragma unroll
            for (int j = 0; j < 4; j++) {
                nBv[j] = dbl[(t + 4 + j) * 64 + Rq + s];
                nCv[j] = dbl[(t + 4 + j) * 64 + Rq + Sq + s];
            }
            if (s == 0) {
                #pragma unroll
                for (int j = 0; j < 4; j++) nzv[j] = zp[(size_t)(t + 4 + j) * (2*Eq)];
            }
        }

        float d[4] = {dv.x, dv.y, dv.z, dv.w};
        float u[4] = {uv.x, uv.y, uv.z, uv.w};
        float ea[4], p[4];
        #pragma unroll
        for (int j = 0; j < 4; j++) ea[j] = __expf(d[j] * A);
        #pragma unroll
        for (int j = 0; j < 4; j++) {
            h = ea[j] * h + (d[j] * u[j]) * Bv[j];
            p[j] = h * Cv[j];
        }
        #pragma unroll
        for (int o2 = 8; o2; o2 >>= 1) {
            #pragma unroll
            for (int j = 0; j < 4; j++)
                p[j] += __shfl_xor_sync(~0u, p[j], o2);
        }
        if (s == 0) {
            #pragma unroll
            for (int j = 0; j < 4; j++) {
                float yv = p[j] + Dv * u[j];
                float z = zv[j];
                yv *= z / (1.f + __expf(-z));
                yp[(size_t)(t + j) * Eq] = __float2bfloat16(yv);
            }
        }
        if (more) {
            dv = ndv; uv = nuv;
            #pragma unroll
            for (int j = 0; j < 4; j++) { Bv[j] = nBv[j]; Cv[j] = nCv[j]; }
            if (s == 0) {
                #pragma unroll
                for (int j = 0; j < 4; j++) zv[j] = nzv[j];
            }
        }
    }
}

// ---------------- launch ----------------
extern "C" void kernel_launch(void* const* d_in, const int* in_sizes, int n_in,
                              void* d_out, int out_size)
{
    const float* x       = (const float*)d_in[0];
    const float* cond    = (const float*)d_in[1];
    const float* ln_g    = (const float*)d_in[2];
    const float* ln_b    = (const float*)d_in[3];
    const float* W_in    = (const float*)d_in[4];
    const float* conv_w  = (const float*)d_in[5];
    const float* conv_b  = (const float*)d_in[6];
    const float* W_x     = (const float*)d_in[7];
    const float* W_dt    = (const float*)d_in[8];
    const float* b_dt    = (const float*)d_in[9];
    const float* A_log   = (const float*)d_in[10];
    const float* D_skip  = (const float*)d_in[11];
    const float* W_out   = (const float*)d_in[12];
    const float* film_gw = (const float*)d_in[13];
    const float* film_gb = (const float*)d_in[14];
    const float* film_bw = (const float*)d_in[15];
    const float* film_bb = (const float*)d_in[16];
    float* out = (float*)d_out;

    __nv_bfloat16 *xnb, *yb, *wt_in, *wt_out;
    float *xz, *uc, *ucT, *xpart, *xdbl, *deltaT, *hfin, *aprod, *gamma, *beta;
    cudaGetSymbolAddress((void**)&xnb,    g_xnb);
    cudaGetSymbolAddress((void**)&xz,     g_xz);
    cudaGetSymbolAddress((void**)&uc,     g_uc);
    cudaGetSymbolAddress((void**)&ucT,    g_ucT);
    cudaGetSymbolAddress((void**)&xpart,  g_xpart);
    cudaGetSymbolAddress((void**)&xdbl,   g_xdbl);
    cudaGetSymbolAddress((void**)&deltaT, g_deltaT);
    cudaGetSymbolAddress((void**)&yb,     g_yb);
    cudaGetSymbolAddress((void**)&hfin,   g_hfin);
    cudaGetSymbolAddress((void**)&aprod,  g_aprod);
    cudaGetSymbolAddress((void**)&gamma,  g_gamma);
    cudaGetSymbolAddress((void**)&beta,   g_beta);
    cudaGetSymbolAddress((void**)&wt_in,  g_wt_in);
    cudaGetSymbolAddress((void**)&wt_out, g_wt_out);

    // 1. fused prep: transposes + LN + FiLM params
    prep_kernel<<<PREP_BLOCKS, 256>>>(x, ln_g, ln_b, W_in, W_out, cond,
                                      film_gw, film_gb, film_bw, film_bb,
                                      xnb, wt_in, wt_out, gamma, beta);
    // 2. in_proj (BN=64, 3-stage)
    gemm_bf16<64,0><<<dim3(2*Eq/64, Mtok/128), 256>>>(
        xnb, wt_in, xz, Dq, Dq, Dq, 2*Eq, nullptr, nullptr);
    // 3. conv + SiLU -> uc (token-major) + ucT (e-major)
    conv_silu_kernel<<<2048, 256>>>(xz, conv_w, conv_b, uc, ucT);
    // 4. x_proj split-K=8 (token-major uc)
    gemm_tf32<32,64,16,1,4,0><<<dim3(1, Mtok/32, XSPLIT), 128>>>(
        uc, W_x, xpart, Eq/XSPLIT, Eq, Rq + 2*Sq, Rq + 2*Sq, nullptr, nullptr,
        Eq/XSPLIT, (size_t)Mtok * 64);
    reduce_xpart<<<Mtok*64/1024, 256>>>(xpart, xdbl);
    // 5. dt_proj + softplus -> deltaT (e-major, transposed store)
    gemm_tf32<128,128,16,4,2,2><<<dim3(Eq/128, Mtok/128), 256>>>(
        xdbl, W_dt, deltaT, Rq, Rq + 2*Sq, Eq, Eq, nullptr, b_dt, 0, 0);
    // 6. scan pass1 (chunk summaries)
    scan_pass1<<<Bq*64*NCH, 256>>>(A_log, xdbl, deltaT, ucT, hfin, aprod);
    // 7. scan pass3 with lookback carry
    scan_pass3<<<Bq*64*NCH, 256>>>(A_log, D_skip, xdbl, deltaT, ucT, xz, hfin, aprod, yb);
    // 8. out_proj + FiLM (BN=64, 3-stage)
    gemm_bf16<64,1><<<dim3(Dq/64, Mtok/128), 256>>>(
        yb, wt_out, out, Eq, Eq, Eq, Dq, gamma, beta);
}